// round 14
// baseline (speedup 1.0000x reference)
#include <cuda_runtime.h>
#include <cuda_bf16.h>
#include <stdint.h>
#include <math.h>

// ---------------- problem dims ----------------
#define BQ       4096
#define NEX      20000
#define NPAD     20096               // 157 * 128
#define FDIM     768
#define EDIM     512
#define TOTROWS  (BQ + NPAD)         // 24192
#define REALROWS (BQ + NEX)          // 24096
#define NBN      157

// ---------------- scratch (.bss, zero-init; pads stay 0) ----------------
__device__ float         g_XDe[(size_t)TOTROWS * EDIM];   // fp32 embeds (pre-norm)
__device__ __nv_bfloat16 g_fhi[(size_t)TOTROWS * FDIM];   // [X;D] features hi
__device__ __nv_bfloat16 g_flo[(size_t)TOTROWS * FDIM];   // lo
__device__ __nv_bfloat16 g_whi[(size_t)EDIM * FDIM];      // g_w hi
__device__ __nv_bfloat16 g_wlo[(size_t)EDIM * FDIM];
__device__ __nv_bfloat16 g_hi[(size_t)TOTROWS * EDIM];    // normalized embeds hi
__device__ __nv_bfloat16 g_lo[(size_t)TOTROWS * EDIM];    // lo
__device__ float         g_rh[NPAD];                       // rh (pad = 0)
__device__ float         g_partial[NBN * BQ];

// ---------------- helpers (base-target instructions only) ----------------
__device__ __forceinline__ void ldsm4(uint32_t& r0, uint32_t& r1,
                                      uint32_t& r2, uint32_t& r3, uint32_t addr) {
    asm volatile("ldmatrix.sync.aligned.m8n8.x4.shared.b16 {%0,%1,%2,%3}, [%4];"
                 : "=r"(r0), "=r"(r1), "=r"(r2), "=r"(r3) : "r"(addr));
}
__device__ __forceinline__ void mma_bf16(float* c, const uint32_t* a,
                                         uint32_t b0, uint32_t b1) {
    asm volatile(
        "mma.sync.aligned.m16n8k16.row.col.f32.bf16.bf16.f32 "
        "{%0,%1,%2,%3},{%4,%5,%6,%7},{%8,%9},{%0,%1,%2,%3};"
        : "+f"(c[0]), "+f"(c[1]), "+f"(c[2]), "+f"(c[3])
        : "r"(a[0]), "r"(a[1]), "r"(a[2]), "r"(a[3]), "r"(b0), "r"(b1));
}
__device__ __forceinline__ void cp16(uint32_t dst, const void* src) {
    asm volatile("cp.async.cg.shared.global [%0], [%1], 16;"
                 :: "r"(dst), "l"(src) : "memory");
}
// SW128 swizzle within a 16KB subtile of 128B rows
#define SW(b) ((b) ^ (((b) >> 3) & 0x70))

// ---------------------------------------------------------------------------
// Unified 3-pass bf16-split GEMM — R10/R13 config (CTA 128x128, warp 32x64,
// BK=32, 3-stage cp.async, 1 sync/chunk) + warp phase staggering:
// each m-warp starts at a different B ng-group; the two n-warp-halves walk
// the ks slices in opposite order. Breaks the post-barrier LDSM convoy.
// ---------------------------------------------------------------------------
#define STG    32768
#define NSTAGE 3
#define SMEM_GEMM (512 + NSTAGE * STG)    // 98816

template <int MODE>
__global__ __launch_bounds__(256, 2) void gemm_kernel(const float* __restrict__ coef_in)
{
    constexpr int K = (MODE == 0) ? FDIM : EDIM;
    constexpr int NK = K / 32;

    extern __shared__ char smem[];
    const uint32_t smem_u = (uint32_t)__cvta_generic_to_shared(smem);
    float* scoef = (float*)smem;

    const int tid = threadIdx.x;
    const int wid = tid >> 5, lane = tid & 31;
    const int wm = wid & 3, wn = wid >> 2;
    const int m0 = blockIdx.x * 128, n0 = blockIdx.y * 128;

    const __nv_bfloat16 *Ah, *Al, *Bh, *Bl;
    if (MODE == 0) {
        Ah = g_fhi; Al = g_flo; Bh = g_whi; Bl = g_wlo;
    } else {
        Ah = g_hi; Al = g_lo;
        Bh = g_hi + (size_t)BQ * EDIM; Bl = g_lo + (size_t)BQ * EDIM;
    }

    if (tid < 128)
        scoef[tid] = (MODE == 0) ? coef_in[n0 + tid] : g_rh[n0 + tid];

    // Precomputed swizzled ldsm bases (per-warp constants).
    uint32_t aBase[2][2], bBase[2][4];
#pragma unroll
    for (int comp = 0; comp < 2; comp++) {
#pragma unroll
        for (int mt = 0; mt < 2; mt++) {
            uint32_t row = wm * 32 + mt * 16 + (lane & 15);
            aBase[comp][mt] = SW((uint32_t)(row * 128 + comp * 64));
        }
#pragma unroll
        for (int ng = 0; ng < 4; ng++) {
            uint32_t nr = wn * 64 + ng * 16 + (lane & 15);
            bBase[comp][ng] = SW((uint32_t)(nr * 128 + comp * 64)) + 16384u;
        }
    }

    auto issue_load = [&](int chunk, int st_idx) {
        const int k0 = chunk * 32;
        const uint32_t st = smem_u + 512 + st_idx * STG;
#pragma unroll
        for (int t = 0; t < 8; t++) {
            int idx = t * 256 + tid;                // [0,2048)
            int mat = idx >> 10;                    // 0=A, 1=B
            int rid = (idx & 1023) >> 3;            // row 0..127
            int seg = idx & 7;                      // 0-3 hi, 4-7 lo
            int comp = seg >> 2, ks8 = seg & 3;
            size_t gofs = (size_t)((mat ? n0 : m0) + rid) * K + k0 + ks8 * 8;
            const __nv_bfloat16* src =
                mat ? (comp ? Bl : Bh) : (comp ? Al : Ah);
            uint32_t d = SW((uint32_t)(rid * 128 + seg * 16));
            cp16(st + mat * 16384 + d, src + gofs);
        }
        asm volatile("cp.async.commit_group;" ::: "memory");
    };

    float facc[2][8][4];
#pragma unroll
    for (int mt = 0; mt < 2; mt++)
#pragma unroll
        for (int nt = 0; nt < 8; nt++)
#pragma unroll
            for (int i = 0; i < 4; i++) facc[mt][nt][i] = 0.f;

    issue_load(0, 0);
    issue_load(1, 1);

    int s = 0;
    for (int chunk = 0; chunk < NK; chunk++) {
        if (chunk + 1 < NK) {
            asm volatile("cp.async.wait_group 1;" ::: "memory");
        } else {
            asm volatile("cp.async.wait_group 0;" ::: "memory");
        }
        __syncthreads();   // stage s ready; all warps done with stage (s+2)%3

        if (chunk + 2 < NK) issue_load(chunk + 2, (s + 2) % NSTAGE);

        const uint32_t st = smem_u + 512 + s * STG;
#pragma unroll
        for (int kj = 0; kj < 2; kj++) {
            const int ks = kj ^ wn;                 // n-halves walk ks oppositely
            const uint32_t kb = (uint32_t)(ks * 32 + (lane >> 4) * 16);
            uint32_t a[2][2][4];
#pragma unroll
            for (int comp = 0; comp < 2; comp++)
#pragma unroll
                for (int mt = 0; mt < 2; mt++)
                    ldsm4(a[comp][mt][0], a[comp][mt][1], a[comp][mt][2], a[comp][mt][3],
                          st + (aBase[comp][mt] ^ kb));
#pragma unroll
            for (int j = 0; j < 4; j++) {
                const int ng = (j + wm) & 3;        // m-warps start on different B groups
                uint32_t bh4[4], bl4[4];
                ldsm4(bh4[0], bh4[1], bh4[2], bh4[3], st + (bBase[0][ng] ^ kb));
                ldsm4(bl4[0], bl4[1], bl4[2], bl4[3], st + (bBase[1][ng] ^ kb));
#pragma unroll
                for (int p = 0; p < 3; p++) {
                    const uint32_t (*aa)[4] = (p == 2) ? &a[1][0] : &a[0][0];
                    const uint32_t* bb = (p == 1) ? bl4 : bh4;
#pragma unroll
                    for (int mt = 0; mt < 2; mt++)
#pragma unroll
                        for (int h = 0; h < 2; h++)
                            mma_bf16(facc[mt][ng * 2 + h], aa[mt], bb[h], bb[2 + h]);
                }
            }
        }
        s = (s + 1) % NSTAGE;
    }

    if (MODE == 0) {
        // +bias, store fp32
#pragma unroll
        for (int mt = 0; mt < 2; mt++)
#pragma unroll
            for (int nt = 0; nt < 8; nt++)
#pragma unroll
                for (int p = 0; p < 2; p++) {
                    int row = m0 + wm * 32 + mt * 16 + p * 8 + (lane >> 2);
                    if (row >= REALROWS) continue;
                    int cl = wn * 64 + nt * 8 + (lane & 3) * 2;
                    float2 v;
                    v.x = facc[mt][nt][p * 2 + 0] + scoef[cl];
                    v.y = facc[mt][nt][p * 2 + 1] + scoef[cl + 1];
                    *(float2*)&g_XDe[(size_t)row * EDIM + n0 + cl] = v;
                }
    } else {
        // cube * rh, reduce over n
        float rsum[4] = {0.f, 0.f, 0.f, 0.f};
#pragma unroll
        for (int mt = 0; mt < 2; mt++)
#pragma unroll
            for (int nt = 0; nt < 8; nt++)
#pragma unroll
                for (int i = 0; i < 4; i++) {
                    int cl = wn * 64 + nt * 8 + (lane & 3) * 2 + (i & 1);
                    float a = facc[mt][nt][i];
                    rsum[mt * 2 + (i >> 1)] += a * a * a * scoef[cl];
                }
#pragma unroll
        for (int off = 1; off <= 2; off <<= 1)
#pragma unroll
            for (int k = 0; k < 4; k++)
                rsum[k] += __shfl_xor_sync(0xffffffffu, rsum[k], off);

        __syncthreads();                       // stages dead after this
        float* red = (float*)(smem + 512);
        if ((lane & 3) == 0) {
#pragma unroll
            for (int mt = 0; mt < 2; mt++)
#pragma unroll
                for (int h = 0; h < 2; h++)
                    red[wn * 128 + wm * 32 + mt * 16 + h * 8 + (lane >> 2)] =
                        rsum[mt * 2 + h];
        }
        __syncthreads();
        if (tid < 128)
            g_partial[(size_t)blockIdx.y * BQ + m0 + tid] = red[tid] + red[128 + tid];
    }
}

// ---------------------------------------------------------------------------
// Convert fp32 -> bf16 hi/lo (float4 vectorized); rh fused at the tail.
// ---------------------------------------------------------------------------
#define NX    (BQ * FDIM)
#define NREAL (REALROWS * FDIM)
#define NW    (EDIM * FDIM)
#define NV4   ((NREAL + NW) / 4)

__global__ void convert_all_kernel(const float* __restrict__ X,
                                   const float* __restrict__ D,
                                   const float* __restrict__ Wg,
                                   const float* __restrict__ r,
                                   const float* __restrict__ h_w,
                                   const float* __restrict__ h_b)
{
    const int tid0 = blockIdx.x * blockDim.x + threadIdx.x;
    const int stride = gridDim.x * blockDim.x;

    for (int j = tid0; j < NV4; j += stride) {
        const int e = j * 4;
        float4 v;
        __nv_bfloat16 *dhi, *dlo;
        int o;
        if (e < NX)          { v = *(const float4*)(X + e);            dhi = g_fhi; dlo = g_flo; o = e; }
        else if (e < NREAL)  { v = *(const float4*)(D + (e - NX));     dhi = g_fhi; dlo = g_flo; o = e; }
        else                 { v = *(const float4*)(Wg + (e - NREAL)); dhi = g_whi; dlo = g_wlo; o = e - NREAL; }
        __nv_bfloat16 h0 = __float2bfloat16(v.x), h1 = __float2bfloat16(v.y);
        __nv_bfloat16 h2 = __float2bfloat16(v.z), h3 = __float2bfloat16(v.w);
        __nv_bfloat162 H0; H0.x = h0; H0.y = h1;
        __nv_bfloat162 H1; H1.x = h2; H1.y = h3;
        __nv_bfloat162 L0, L1;
        L0.x = __float2bfloat16(v.x - __bfloat162float(h0));
        L0.y = __float2bfloat16(v.y - __bfloat162float(h1));
        L1.x = __float2bfloat16(v.z - __bfloat162float(h2));
        L1.y = __float2bfloat16(v.w - __bfloat162float(h3));
        *(__nv_bfloat162*)&dhi[o]     = H0;
        *(__nv_bfloat162*)&dhi[o + 2] = H1;
        *(__nv_bfloat162*)&dlo[o]     = L0;
        *(__nv_bfloat162*)&dlo[o + 2] = L1;
    }
    for (int n = tid0; n < NEX; n += stride)
        g_rh[n] = (2.f * r[n] - 1.f) * h_w[0] + h_b[0];
}

__global__ __launch_bounds__(128) void normalize_kernel()
{
    const int row = blockIdx.x;
    const float* p = g_XDe + (size_t)row * EDIM;
    const int t = threadIdx.x;
    float v[4];
    float ss = 0.f;
#pragma unroll
    for (int i = 0; i < 4; i++) { v[i] = p[t + i * 128]; ss += v[i] * v[i]; }
#pragma unroll
    for (int off = 16; off >= 1; off >>= 1)
        ss += __shfl_xor_sync(0xffffffffu, ss, off);
    __shared__ float red[4];
    if ((t & 31) == 0) red[t >> 5] = ss;
    __syncthreads();
    float inv = 1.f / fmaxf(sqrtf(red[0] + red[1] + red[2] + red[3]), 1e-12f);
#pragma unroll
    for (int i = 0; i < 4; i++) {
        float nv = v[i] * inv;
        __nv_bfloat16 h = __float2bfloat16(nv);
        g_hi[(size_t)row * EDIM + t + i * 128] = h;
        g_lo[(size_t)row * EDIM + t + i * 128] =
            __float2bfloat16(nv - __bfloat162float(h));
    }
}

__global__ void reduce_kernel(float* __restrict__ out, int out_size)
{
    int b = blockIdx.x * blockDim.x + threadIdx.x;
    if (b >= BQ) return;
    float s = 0.f;
#pragma unroll 4
    for (int j = 0; j < NBN; j++) s += g_partial[(size_t)j * BQ + b];
    if (b < out_size) out[b] = s;
    if (BQ + b < out_size) out[BQ + b] = 1.f / (1.f + expf(-s));
}

// ---------------------------------------------------------------------------
extern "C" void kernel_launch(void* const* d_in, const int* in_sizes, int n_in,
                              void* d_out, int out_size)
{
    const float* X   = (const float*)d_in[0];
    const float* D   = (const float*)d_in[1];
    const float* r   = (const float*)d_in[2];
    const float* g_w = (const float*)d_in[3];
    const float* g_b = (const float*)d_in[4];
    const float* h_w = (const float*)d_in[5];
    const float* h_b = (const float*)d_in[6];
    float* out = (float*)d_out;

    cudaFuncSetAttribute(gemm_kernel<0>,
                         cudaFuncAttributeMaxDynamicSharedMemorySize, SMEM_GEMM);
    cudaFuncSetAttribute(gemm_kernel<1>,
                         cudaFuncAttributeMaxDynamicSharedMemorySize, SMEM_GEMM);

    // launch 0: convert + rh
    convert_all_kernel<<<1184, 256>>>(X, D, g_w, r, h_w, h_b);

    // launch 1: embed GEMM (bf16 3-pass)
    dim3 ge(TOTROWS / 128, EDIM / 128);        // (189, 4)
    gemm_kernel<0><<<ge, 256, SMEM_GEMM>>>(g_b);

    // launch 2: normalize -> bf16 hi/lo
    normalize_kernel<<<REALROWS, 128>>>();

    // launch 3: main GEMM (fused cube*rh + n-reduction)  <- ncu capture slot
    dim3 gm(BQ / 128, NPAD / 128);             // (32, 157)
    gemm_kernel<1><<<gm, 256, SMEM_GEMM>>>(nullptr);

    // launch 4: final reduce + sigmoid
    reduce_kernel<<<(BQ + 127) / 128, 128>>>(out, out_size);
}

// round 15
// speedup vs baseline: 2.6008x; 2.6008x over previous
#include <cuda_runtime.h>
#include <cuda_bf16.h>
#include <stdint.h>
#include <math.h>

// ---------------- problem dims ----------------
#define BQ       4096
#define NEX      20000
#define NPAD     20096               // 157 * 128
#define FDIM     768
#define EDIM     512
#define TOTROWS  (BQ + NPAD)         // 24192
#define REALROWS (BQ + NEX)          // 24096
#define NBN      157

// ---------------- scratch (.bss, zero-init; pads stay 0) ----------------
__device__ float         g_XDe[(size_t)TOTROWS * EDIM];   // fp32 embeds (pre-norm)
__device__ __nv_bfloat16 g_fhi[(size_t)TOTROWS * FDIM];   // [X;D] features hi
__device__ __nv_bfloat16 g_flo[(size_t)TOTROWS * FDIM];   // lo
__device__ __nv_bfloat16 g_whi[(size_t)EDIM * FDIM];      // g_w hi
__device__ __nv_bfloat16 g_wlo[(size_t)EDIM * FDIM];
__device__ __nv_bfloat16 g_hi[(size_t)TOTROWS * EDIM];    // normalized embeds hi
__device__ __nv_bfloat16 g_lo[(size_t)TOTROWS * EDIM];    // lo
__device__ float         g_rh[NPAD];                       // rh (pad = 0)
__device__ float         g_partial[NBN * BQ];

// ---------------- helpers (base-target instructions only) ----------------
__device__ __forceinline__ void ldsm4(uint32_t& r0, uint32_t& r1,
                                      uint32_t& r2, uint32_t& r3, uint32_t addr) {
    asm volatile("ldmatrix.sync.aligned.m8n8.x4.shared.b16 {%0,%1,%2,%3}, [%4];"
                 : "=r"(r0), "=r"(r1), "=r"(r2), "=r"(r3) : "r"(addr));
}
__device__ __forceinline__ void mma_bf16(float* c, const uint32_t* a,
                                         uint32_t b0, uint32_t b1) {
    asm volatile(
        "mma.sync.aligned.m16n8k16.row.col.f32.bf16.bf16.f32 "
        "{%0,%1,%2,%3},{%4,%5,%6,%7},{%8,%9},{%0,%1,%2,%3};"
        : "+f"(c[0]), "+f"(c[1]), "+f"(c[2]), "+f"(c[3])
        : "r"(a[0]), "r"(a[1]), "r"(a[2]), "r"(a[3]), "r"(b0), "r"(b1));
}
__device__ __forceinline__ void cp16(uint32_t dst, const void* src) {
    asm volatile("cp.async.cg.shared.global [%0], [%1], 16;"
                 :: "r"(dst), "l"(src) : "memory");
}
// SW128 swizzle within a 16KB subtile of 128B rows
#define SW(b) ((b) ^ (((b) >> 3) & 0x70))

// ---------------------------------------------------------------------------
// Unified 3-pass bf16-split GEMM — R13 config (CTA 128x128, warp 32x64, BK=32,
// 3-stage cp.async, 1 sync/chunk, precomputed swizzled ldsm bases) + the SAFE
// half of the warp stagger: the two n-warp-halves walk the two ks slices in
// opposite order (address-only permutation; all register subscripts static).
// ---------------------------------------------------------------------------
#define STG    32768
#define NSTAGE 3
#define SMEM_GEMM (512 + NSTAGE * STG)    // 98816

template <int MODE>
__global__ __launch_bounds__(256, 2) void gemm_kernel(const float* __restrict__ coef_in)
{
    constexpr int K = (MODE == 0) ? FDIM : EDIM;
    constexpr int NK = K / 32;

    extern __shared__ char smem[];
    const uint32_t smem_u = (uint32_t)__cvta_generic_to_shared(smem);
    float* scoef = (float*)smem;

    const int tid = threadIdx.x;
    const int wid = tid >> 5, lane = tid & 31;
    const int wm = wid & 3, wn = wid >> 2;
    const int m0 = blockIdx.x * 128, n0 = blockIdx.y * 128;

    const __nv_bfloat16 *Ah, *Al, *Bh, *Bl;
    if (MODE == 0) {
        Ah = g_fhi; Al = g_flo; Bh = g_whi; Bl = g_wlo;
    } else {
        Ah = g_hi; Al = g_lo;
        Bh = g_hi + (size_t)BQ * EDIM; Bl = g_lo + (size_t)BQ * EDIM;
    }

    if (tid < 128)
        scoef[tid] = (MODE == 0) ? coef_in[n0 + tid] : g_rh[n0 + tid];

    // Precomputed swizzled ldsm bases (per-warp constants).
    uint32_t aBase[2][2], bBase[2][4];
#pragma unroll
    for (int comp = 0; comp < 2; comp++) {
#pragma unroll
        for (int mt = 0; mt < 2; mt++) {
            uint32_t row = wm * 32 + mt * 16 + (lane & 15);
            aBase[comp][mt] = SW((uint32_t)(row * 128 + comp * 64));
        }
#pragma unroll
        for (int ng = 0; ng < 4; ng++) {
            uint32_t nr = wn * 64 + ng * 16 + (lane & 15);
            bBase[comp][ng] = SW((uint32_t)(nr * 128 + comp * 64)) + 16384u;
        }
    }

    auto issue_load = [&](int chunk, int st_idx) {
        const int k0 = chunk * 32;
        const uint32_t st = smem_u + 512 + st_idx * STG;
#pragma unroll
        for (int t = 0; t < 8; t++) {
            int idx = t * 256 + tid;                // [0,2048)
            int mat = idx >> 10;                    // 0=A, 1=B
            int rid = (idx & 1023) >> 3;            // row 0..127
            int seg = idx & 7;                      // 0-3 hi, 4-7 lo
            int comp = seg >> 2, ks8 = seg & 3;
            size_t gofs = (size_t)((mat ? n0 : m0) + rid) * K + k0 + ks8 * 8;
            const __nv_bfloat16* src =
                mat ? (comp ? Bl : Bh) : (comp ? Al : Ah);
            uint32_t d = SW((uint32_t)(rid * 128 + seg * 16));
            cp16(st + mat * 16384 + d, src + gofs);
        }
        asm volatile("cp.async.commit_group;" ::: "memory");
    };

    float facc[2][8][4];
#pragma unroll
    for (int mt = 0; mt < 2; mt++)
#pragma unroll
        for (int nt = 0; nt < 8; nt++)
#pragma unroll
            for (int i = 0; i < 4; i++) facc[mt][nt][i] = 0.f;

    issue_load(0, 0);
    issue_load(1, 1);

    int s = 0;
    for (int chunk = 0; chunk < NK; chunk++) {
        if (chunk + 1 < NK) {
            asm volatile("cp.async.wait_group 1;" ::: "memory");
        } else {
            asm volatile("cp.async.wait_group 0;" ::: "memory");
        }
        __syncthreads();   // stage s ready; all warps done with stage (s+2)%3

        if (chunk + 2 < NK) issue_load(chunk + 2, (s + 2) % NSTAGE);

        const uint32_t st = smem_u + 512 + s * STG;
#pragma unroll
        for (int kj = 0; kj < 2; kj++) {
            const int ks = kj ^ wn;                 // address-only stagger
            const uint32_t kb = (uint32_t)(ks * 32 + (lane >> 4) * 16);
            uint32_t a[2][2][4];
#pragma unroll
            for (int comp = 0; comp < 2; comp++)
#pragma unroll
                for (int mt = 0; mt < 2; mt++)
                    ldsm4(a[comp][mt][0], a[comp][mt][1], a[comp][mt][2], a[comp][mt][3],
                          st + (aBase[comp][mt] ^ kb));
#pragma unroll
            for (int ng = 0; ng < 4; ng++) {        // static ng: no reg spill
                uint32_t bh4[4], bl4[4];
                ldsm4(bh4[0], bh4[1], bh4[2], bh4[3], st + (bBase[0][ng] ^ kb));
                ldsm4(bl4[0], bl4[1], bl4[2], bl4[3], st + (bBase[1][ng] ^ kb));
#pragma unroll
                for (int p = 0; p < 3; p++) {
                    const uint32_t (*aa)[4] = (p == 2) ? &a[1][0] : &a[0][0];
                    const uint32_t* bb = (p == 1) ? bl4 : bh4;
#pragma unroll
                    for (int mt = 0; mt < 2; mt++)
#pragma unroll
                        for (int h = 0; h < 2; h++)
                            mma_bf16(facc[mt][ng * 2 + h], aa[mt], bb[h], bb[2 + h]);
                }
            }
        }
        s = (s + 1) % NSTAGE;
    }

    if (MODE == 0) {
        // +bias, store fp32
#pragma unroll
        for (int mt = 0; mt < 2; mt++)
#pragma unroll
            for (int nt = 0; nt < 8; nt++)
#pragma unroll
                for (int p = 0; p < 2; p++) {
                    int row = m0 + wm * 32 + mt * 16 + p * 8 + (lane >> 2);
                    if (row >= REALROWS) continue;
                    int cl = wn * 64 + nt * 8 + (lane & 3) * 2;
                    float2 v;
                    v.x = facc[mt][nt][p * 2 + 0] + scoef[cl];
                    v.y = facc[mt][nt][p * 2 + 1] + scoef[cl + 1];
                    *(float2*)&g_XDe[(size_t)row * EDIM + n0 + cl] = v;
                }
    } else {
        // cube * rh, reduce over n
        float rsum[4] = {0.f, 0.f, 0.f, 0.f};
#pragma unroll
        for (int mt = 0; mt < 2; mt++)
#pragma unroll
            for (int nt = 0; nt < 8; nt++)
#pragma unroll
                for (int i = 0; i < 4; i++) {
                    int cl = wn * 64 + nt * 8 + (lane & 3) * 2 + (i & 1);
                    float a = facc[mt][nt][i];
                    rsum[mt * 2 + (i >> 1)] += a * a * a * scoef[cl];
                }
#pragma unroll
        for (int off = 1; off <= 2; off <<= 1)
#pragma unroll
            for (int k = 0; k < 4; k++)
                rsum[k] += __shfl_xor_sync(0xffffffffu, rsum[k], off);

        __syncthreads();                       // stages dead after this
        float* red = (float*)(smem + 512);
        if ((lane & 3) == 0) {
#pragma unroll
            for (int mt = 0; mt < 2; mt++)
#pragma unroll
                for (int h = 0; h < 2; h++)
                    red[wn * 128 + wm * 32 + mt * 16 + h * 8 + (lane >> 2)] =
                        rsum[mt * 2 + h];
        }
        __syncthreads();
        if (tid < 128)
            g_partial[(size_t)blockIdx.y * BQ + m0 + tid] = red[tid] + red[128 + tid];
    }
}

// ---------------------------------------------------------------------------
// Convert fp32 -> bf16 hi/lo (float4 vectorized); rh fused at the tail.
// ---------------------------------------------------------------------------
#define NX    (BQ * FDIM)
#define NREAL (REALROWS * FDIM)
#define NW    (EDIM * FDIM)
#define NV4   ((NREAL + NW) / 4)

__global__ void convert_all_kernel(const float* __restrict__ X,
                                   const float* __restrict__ D,
                                   const float* __restrict__ Wg,
                                   const float* __restrict__ r,
                                   const float* __restrict__ h_w,
                                   const float* __restrict__ h_b)
{
    const int tid0 = blockIdx.x * blockDim.x + threadIdx.x;
    const int stride = gridDim.x * blockDim.x;

    for (int j = tid0; j < NV4; j += stride) {
        const int e = j * 4;
        float4 v;
        __nv_bfloat16 *dhi, *dlo;
        int o;
        if (e < NX)          { v = *(const float4*)(X + e);            dhi = g_fhi; dlo = g_flo; o = e; }
        else if (e < NREAL)  { v = *(const float4*)(D + (e - NX));     dhi = g_fhi; dlo = g_flo; o = e; }
        else                 { v = *(const float4*)(Wg + (e - NREAL)); dhi = g_whi; dlo = g_wlo; o = e - NREAL; }
        __nv_bfloat16 h0 = __float2bfloat16(v.x), h1 = __float2bfloat16(v.y);
        __nv_bfloat16 h2 = __float2bfloat16(v.z), h3 = __float2bfloat16(v.w);
        __nv_bfloat162 H0; H0.x = h0; H0.y = h1;
        __nv_bfloat162 H1; H1.x = h2; H1.y = h3;
        __nv_bfloat162 L0, L1;
        L0.x = __float2bfloat16(v.x - __bfloat162float(h0));
        L0.y = __float2bfloat16(v.y - __bfloat162float(h1));
        L1.x = __float2bfloat16(v.z - __bfloat162float(h2));
        L1.y = __float2bfloat16(v.w - __bfloat162float(h3));
        *(__nv_bfloat162*)&dhi[o]     = H0;
        *(__nv_bfloat162*)&dhi[o + 2] = H1;
        *(__nv_bfloat162*)&dlo[o]     = L0;
        *(__nv_bfloat162*)&dlo[o + 2] = L1;
    }
    for (int n = tid0; n < NEX; n += stride)
        g_rh[n] = (2.f * r[n] - 1.f) * h_w[0] + h_b[0];
}

__global__ __launch_bounds__(128) void normalize_kernel()
{
    const int row = blockIdx.x;
    const float* p = g_XDe + (size_t)row * EDIM;
    const int t = threadIdx.x;
    float v[4];
    float ss = 0.f;
#pragma unroll
    for (int i = 0; i < 4; i++) { v[i] = p[t + i * 128]; ss += v[i] * v[i]; }
#pragma unroll
    for (int off = 16; off >= 1; off >>= 1)
        ss += __shfl_xor_sync(0xffffffffu, ss, off);
    __shared__ float red[4];
    if ((t & 31) == 0) red[t >> 5] = ss;
    __syncthreads();
    float inv = 1.f / fmaxf(sqrtf(red[0] + red[1] + red[2] + red[3]), 1e-12f);
#pragma unroll
    for (int i = 0; i < 4; i++) {
        float nv = v[i] * inv;
        __nv_bfloat16 h = __float2bfloat16(nv);
        g_hi[(size_t)row * EDIM + t + i * 128] = h;
        g_lo[(size_t)row * EDIM + t + i * 128] =
            __float2bfloat16(nv - __bfloat162float(h));
    }
}

__global__ void reduce_kernel(float* __restrict__ out, int out_size)
{
    int b = blockIdx.x * blockDim.x + threadIdx.x;
    if (b >= BQ) return;
    float s = 0.f;
#pragma unroll 4
    for (int j = 0; j < NBN; j++) s += g_partial[(size_t)j * BQ + b];
    if (b < out_size) out[b] = s;
    if (BQ + b < out_size) out[BQ + b] = 1.f / (1.f + expf(-s));
}

// ---------------------------------------------------------------------------
extern "C" void kernel_launch(void* const* d_in, const int* in_sizes, int n_in,
                              void* d_out, int out_size)
{
    const float* X   = (const float*)d_in[0];
    const float* D   = (const float*)d_in[1];
    const float* r   = (const float*)d_in[2];
    const float* g_w = (const float*)d_in[3];
    const float* g_b = (const float*)d_in[4];
    const float* h_w = (const float*)d_in[5];
    const float* h_b = (const float*)d_in[6];
    float* out = (float*)d_out;

    cudaFuncSetAttribute(gemm_kernel<0>,
                         cudaFuncAttributeMaxDynamicSharedMemorySize, SMEM_GEMM);
    cudaFuncSetAttribute(gemm_kernel<1>,
                         cudaFuncAttributeMaxDynamicSharedMemorySize, SMEM_GEMM);

    // launch 0: convert + rh
    convert_all_kernel<<<1184, 256>>>(X, D, g_w, r, h_w, h_b);

    // launch 1: embed GEMM (bf16 3-pass)
    dim3 ge(TOTROWS / 128, EDIM / 128);        // (189, 4)
    gemm_kernel<0><<<ge, 256, SMEM_GEMM>>>(g_b);

    // launch 2: normalize -> bf16 hi/lo
    normalize_kernel<<<REALROWS, 128>>>();

    // launch 3: main GEMM (fused cube*rh + n-reduction)  <- ncu capture slot
    dim3 gm(BQ / 128, NPAD / 128);             // (32, 157)
    gemm_kernel<1><<<gm, 256, SMEM_GEMM>>>(nullptr);

    // launch 4: final reduce + sigmoid
    reduce_kernel<<<(BQ + 127) / 128, 128>>>(out, out_size);
}

// round 16
// speedup vs baseline: 2.6328x; 1.0123x over previous
#include <cuda_runtime.h>
#include <cuda_bf16.h>
#include <stdint.h>
#include <math.h>

// ---------------- problem dims ----------------
#define BQ       4096
#define NEX      20000
#define NPAD     20096               // 157 * 128
#define FDIM     768
#define EDIM     512
#define TOTROWS  (BQ + NPAD)         // 24192
#define REALROWS (BQ + NEX)          // 24096
#define NBN      157

// ---------------- scratch (.bss, zero-init; pads stay 0) ----------------
__device__ __nv_bfloat16 g_fhi[(size_t)TOTROWS * FDIM];   // [X;D] features hi
__device__ __nv_bfloat16 g_flo[(size_t)TOTROWS * FDIM];   // lo
__device__ __nv_bfloat16 g_whi[(size_t)EDIM * FDIM];      // g_w hi
__device__ __nv_bfloat16 g_wlo[(size_t)EDIM * FDIM];
__device__ __nv_bfloat16 g_hi[(size_t)TOTROWS * EDIM];    // UNNORMALIZED embeds hi
__device__ __nv_bfloat16 g_lo[(size_t)TOTROWS * EDIM];    // lo
__device__ float         g_sspart[(size_t)8 * TOTROWS];   // per (ntile*2+wn) row ss
__device__ float         g_ci3[BQ];                        // inv_norm^3, query rows
__device__ float         g_crh[NPAD];                      // inv^3 * rh (pad = 0)
__device__ float         g_partial[NBN * BQ];

// ---------------- helpers (base-target instructions only) ----------------
__device__ __forceinline__ void ldsm4(uint32_t& r0, uint32_t& r1,
                                      uint32_t& r2, uint32_t& r3, uint32_t addr) {
    asm volatile("ldmatrix.sync.aligned.m8n8.x4.shared.b16 {%0,%1,%2,%3}, [%4];"
                 : "=r"(r0), "=r"(r1), "=r"(r2), "=r"(r3) : "r"(addr));
}
__device__ __forceinline__ void mma_bf16(float* c, const uint32_t* a,
                                         uint32_t b0, uint32_t b1) {
    asm volatile(
        "mma.sync.aligned.m16n8k16.row.col.f32.bf16.bf16.f32 "
        "{%0,%1,%2,%3},{%4,%5,%6,%7},{%8,%9},{%0,%1,%2,%3};"
        : "+f"(c[0]), "+f"(c[1]), "+f"(c[2]), "+f"(c[3])
        : "r"(a[0]), "r"(a[1]), "r"(a[2]), "r"(a[3]), "r"(b0), "r"(b1));
}
__device__ __forceinline__ void cp16(uint32_t dst, const void* src) {
    asm volatile("cp.async.cg.shared.global [%0], [%1], 16;"
                 :: "r"(dst), "l"(src) : "memory");
}
// SW128 swizzle within a 16KB subtile of 128B rows
#define SW(b) ((b) ^ (((b) >> 3) & 0x70))

// ---------------------------------------------------------------------------
// Unified 3-pass bf16-split GEMM — R13/R15 proven config (CTA 128x128, warp
// 32x64, BK=32, 3-stage cp.async, 1 sync/chunk, precomputed ldsm bases,
// ks-stagger). MODE 0 epilogue now: +bias, write bf16 hi/lo of UNNORMALIZED
// embed + deterministic per-row sum-of-squares partials (normalize deleted).
// MODE 1 epilogue: f^3 * crh reduce, scaled by ci3[m].
// ---------------------------------------------------------------------------
#define STG    32768
#define NSTAGE 3
#define SMEM_GEMM (512 + NSTAGE * STG)    // 98816

template <int MODE>
__global__ __launch_bounds__(256, 2) void gemm_kernel(const float* __restrict__ coef_in)
{
    constexpr int K = (MODE == 0) ? FDIM : EDIM;
    constexpr int NK = K / 32;

    extern __shared__ char smem[];
    const uint32_t smem_u = (uint32_t)__cvta_generic_to_shared(smem);
    float* scoef = (float*)smem;

    const int tid = threadIdx.x;
    const int wid = tid >> 5, lane = tid & 31;
    const int wm = wid & 3, wn = wid >> 2;
    const int m0 = blockIdx.x * 128, n0 = blockIdx.y * 128;

    const __nv_bfloat16 *Ah, *Al, *Bh, *Bl;
    if (MODE == 0) {
        Ah = g_fhi; Al = g_flo; Bh = g_whi; Bl = g_wlo;
    } else {
        Ah = g_hi; Al = g_lo;
        Bh = g_hi + (size_t)BQ * EDIM; Bl = g_lo + (size_t)BQ * EDIM;
    }

    if (tid < 128)
        scoef[tid] = (MODE == 0) ? coef_in[n0 + tid] : g_crh[n0 + tid];

    // Precomputed swizzled ldsm bases (per-warp constants).
    uint32_t aBase[2][2], bBase[2][4];
#pragma unroll
    for (int comp = 0; comp < 2; comp++) {
#pragma unroll
        for (int mt = 0; mt < 2; mt++) {
            uint32_t row = wm * 32 + mt * 16 + (lane & 15);
            aBase[comp][mt] = SW((uint32_t)(row * 128 + comp * 64));
        }
#pragma unroll
        for (int ng = 0; ng < 4; ng++) {
            uint32_t nr = wn * 64 + ng * 16 + (lane & 15);
            bBase[comp][ng] = SW((uint32_t)(nr * 128 + comp * 64)) + 16384u;
        }
    }

    auto issue_load = [&](int chunk, int st_idx) {
        const int k0 = chunk * 32;
        const uint32_t st = smem_u + 512 + st_idx * STG;
#pragma unroll
        for (int t = 0; t < 8; t++) {
            int idx = t * 256 + tid;                // [0,2048)
            int mat = idx >> 10;                    // 0=A, 1=B
            int rid = (idx & 1023) >> 3;            // row 0..127
            int seg = idx & 7;                      // 0-3 hi, 4-7 lo
            int comp = seg >> 2, ks8 = seg & 3;
            size_t gofs = (size_t)((mat ? n0 : m0) + rid) * K + k0 + ks8 * 8;
            const __nv_bfloat16* src =
                mat ? (comp ? Bl : Bh) : (comp ? Al : Ah);
            uint32_t d = SW((uint32_t)(rid * 128 + seg * 16));
            cp16(st + mat * 16384 + d, src + gofs);
        }
        asm volatile("cp.async.commit_group;" ::: "memory");
    };

    float facc[2][8][4];
#pragma unroll
    for (int mt = 0; mt < 2; mt++)
#pragma unroll
        for (int nt = 0; nt < 8; nt++)
#pragma unroll
            for (int i = 0; i < 4; i++) facc[mt][nt][i] = 0.f;

    issue_load(0, 0);
    issue_load(1, 1);

    int s = 0;
    for (int chunk = 0; chunk < NK; chunk++) {
        if (chunk + 1 < NK) {
            asm volatile("cp.async.wait_group 1;" ::: "memory");
        } else {
            asm volatile("cp.async.wait_group 0;" ::: "memory");
        }
        __syncthreads();   // stage s ready; all warps done with stage (s+2)%3

        if (chunk + 2 < NK) issue_load(chunk + 2, (s + 2) % NSTAGE);

        const uint32_t st = smem_u + 512 + s * STG;
#pragma unroll
        for (int kj = 0; kj < 2; kj++) {
            const int ks = kj ^ wn;                 // address-only stagger
            const uint32_t kb = (uint32_t)(ks * 32 + (lane >> 4) * 16);
            uint32_t a[2][2][4];
#pragma unroll
            for (int comp = 0; comp < 2; comp++)
#pragma unroll
                for (int mt = 0; mt < 2; mt++)
                    ldsm4(a[comp][mt][0], a[comp][mt][1], a[comp][mt][2], a[comp][mt][3],
                          st + (aBase[comp][mt] ^ kb));
#pragma unroll
            for (int ng = 0; ng < 4; ng++) {
                uint32_t bh4[4], bl4[4];
                ldsm4(bh4[0], bh4[1], bh4[2], bh4[3], st + (bBase[0][ng] ^ kb));
                ldsm4(bl4[0], bl4[1], bl4[2], bl4[3], st + (bBase[1][ng] ^ kb));
#pragma unroll
                for (int p = 0; p < 3; p++) {
                    const uint32_t (*aa)[4] = (p == 2) ? &a[1][0] : &a[0][0];
                    const uint32_t* bb = (p == 1) ? bl4 : bh4;
#pragma unroll
                    for (int mt = 0; mt < 2; mt++)
#pragma unroll
                        for (int h = 0; h < 2; h++)
                            mma_bf16(facc[mt][ng * 2 + h], aa[mt], bb[h], bb[2 + h]);
                }
            }
        }
        s = (s + 1) % NSTAGE;
    }

    if (MODE == 0) {
        // +bias; write bf16 hi/lo of unnormalized embed; emit ss partials.
#pragma unroll
        for (int mt = 0; mt < 2; mt++)
#pragma unroll
            for (int p = 0; p < 2; p++) {
                const int row = m0 + wm * 32 + mt * 16 + p * 8 + (lane >> 2);
                float ss = 0.f;
                if (row < REALROWS) {
#pragma unroll
                    for (int nt = 0; nt < 8; nt++) {
                        int cl = wn * 64 + nt * 8 + (lane & 3) * 2;
                        float vx = facc[mt][nt][p * 2 + 0] + scoef[cl];
                        float vy = facc[mt][nt][p * 2 + 1] + scoef[cl + 1];
                        ss += vx * vx + vy * vy;
                        __nv_bfloat162 H, L;
                        H.x = __float2bfloat16(vx);
                        H.y = __float2bfloat16(vy);
                        L.x = __float2bfloat16(vx - __bfloat162float(H.x));
                        L.y = __float2bfloat16(vy - __bfloat162float(H.y));
                        *(__nv_bfloat162*)&g_hi[(size_t)row * EDIM + n0 + cl] = H;
                        *(__nv_bfloat162*)&g_lo[(size_t)row * EDIM + n0 + cl] = L;
                    }
                }
                ss += __shfl_xor_sync(0xffffffffu, ss, 1);
                ss += __shfl_xor_sync(0xffffffffu, ss, 2);
                if ((lane & 3) == 0 && row < REALROWS)
                    g_sspart[(size_t)(blockIdx.y * 2 + wn) * TOTROWS + row] = ss;
            }
    } else {
        // f^3 * crh, reduce over n, scale by ci3[m]
        float rsum[4] = {0.f, 0.f, 0.f, 0.f};
#pragma unroll
        for (int mt = 0; mt < 2; mt++)
#pragma unroll
            for (int nt = 0; nt < 8; nt++)
#pragma unroll
                for (int i = 0; i < 4; i++) {
                    int cl = wn * 64 + nt * 8 + (lane & 3) * 2 + (i & 1);
                    float a = facc[mt][nt][i];
                    rsum[mt * 2 + (i >> 1)] += a * a * a * scoef[cl];
                }
#pragma unroll
        for (int off = 1; off <= 2; off <<= 1)
#pragma unroll
            for (int k = 0; k < 4; k++)
                rsum[k] += __shfl_xor_sync(0xffffffffu, rsum[k], off);

        __syncthreads();                       // stages dead after this
        float* red = (float*)(smem + 512);
        if ((lane & 3) == 0) {
#pragma unroll
            for (int mt = 0; mt < 2; mt++)
#pragma unroll
                for (int h = 0; h < 2; h++)
                    red[wn * 128 + wm * 32 + mt * 16 + h * 8 + (lane >> 2)] =
                        rsum[mt * 2 + h];
        }
        __syncthreads();
        if (tid < 128)
            g_partial[(size_t)blockIdx.y * BQ + m0 + tid] =
                (red[tid] + red[128 + tid]) * g_ci3[m0 + tid];
    }
}

// ---------------------------------------------------------------------------
// Convert fp32 -> bf16 hi/lo (float4 vectorized): X, D, g_w.
// ---------------------------------------------------------------------------
#define NX    (BQ * FDIM)
#define NREAL (REALROWS * FDIM)
#define NW    (EDIM * FDIM)
#define NV4   ((NREAL + NW) / 4)

__global__ void convert_all_kernel(const float* __restrict__ X,
                                   const float* __restrict__ D,
                                   const float* __restrict__ Wg)
{
    const int tid0 = blockIdx.x * blockDim.x + threadIdx.x;
    const int stride = gridDim.x * blockDim.x;

    for (int j = tid0; j < NV4; j += stride) {
        const int e = j * 4;
        float4 v;
        __nv_bfloat16 *dhi, *dlo;
        int o;
        if (e < NX)          { v = *(const float4*)(X + e);            dhi = g_fhi; dlo = g_flo; o = e; }
        else if (e < NREAL)  { v = *(const float4*)(D + (e - NX));     dhi = g_fhi; dlo = g_flo; o = e; }
        else                 { v = *(const float4*)(Wg + (e - NREAL)); dhi = g_whi; dlo = g_wlo; o = e - NREAL; }
        __nv_bfloat16 h0 = __float2bfloat16(v.x), h1 = __float2bfloat16(v.y);
        __nv_bfloat16 h2 = __float2bfloat16(v.z), h3 = __float2bfloat16(v.w);
        __nv_bfloat162 H0; H0.x = h0; H0.y = h1;
        __nv_bfloat162 H1; H1.x = h2; H1.y = h3;
        __nv_bfloat162 L0, L1;
        L0.x = __float2bfloat16(v.x - __bfloat162float(h0));
        L0.y = __float2bfloat16(v.y - __bfloat162float(h1));
        L1.x = __float2bfloat16(v.z - __bfloat162float(h2));
        L1.y = __float2bfloat16(v.w - __bfloat162float(h3));
        *(__nv_bfloat162*)&dhi[o]     = H0;
        *(__nv_bfloat162*)&dhi[o + 2] = H1;
        *(__nv_bfloat162*)&dlo[o]     = L0;
        *(__nv_bfloat162*)&dlo[o + 2] = L1;
    }
}

// ---------------------------------------------------------------------------
// invnorm: sum the 8 ss-partials per row; ci3 for queries, crh for exemplars.
// ---------------------------------------------------------------------------
__global__ void invnorm_kernel(const float* __restrict__ r,
                               const float* __restrict__ h_w,
                               const float* __restrict__ h_b)
{
    int i = blockIdx.x * blockDim.x + threadIdx.x;
    if (i >= REALROWS) return;
    float ss = 0.f;
#pragma unroll
    for (int j = 0; j < 8; j++) ss += g_sspart[(size_t)j * TOTROWS + i];
    float inv = 1.f / fmaxf(sqrtf(ss), 1e-12f);
    float c3 = inv * inv * inv;
    if (i < BQ) {
        g_ci3[i] = c3;
    } else {
        int n = i - BQ;
        g_crh[n] = c3 * ((2.f * r[n] - 1.f) * h_w[0] + h_b[0]);
    }
}

__global__ void reduce_kernel(float* __restrict__ out, int out_size)
{
    int b = blockIdx.x * blockDim.x + threadIdx.x;
    if (b >= BQ) return;
    float s = 0.f;
#pragma unroll 4
    for (int j = 0; j < NBN; j++) s += g_partial[(size_t)j * BQ + b];
    if (b < out_size) out[b] = s;
    if (BQ + b < out_size) out[BQ + b] = 1.f / (1.f + expf(-s));
}

// ---------------------------------------------------------------------------
extern "C" void kernel_launch(void* const* d_in, const int* in_sizes, int n_in,
                              void* d_out, int out_size)
{
    const float* X   = (const float*)d_in[0];
    const float* D   = (const float*)d_in[1];
    const float* r   = (const float*)d_in[2];
    const float* g_w = (const float*)d_in[3];
    const float* g_b = (const float*)d_in[4];
    const float* h_w = (const float*)d_in[5];
    const float* h_b = (const float*)d_in[6];
    float* out = (float*)d_out;

    cudaFuncSetAttribute(gemm_kernel<0>,
                         cudaFuncAttributeMaxDynamicSharedMemorySize, SMEM_GEMM);
    cudaFuncSetAttribute(gemm_kernel<1>,
                         cudaFuncAttributeMaxDynamicSharedMemorySize, SMEM_GEMM);

    // launch 0: convert inputs to bf16 hi/lo
    convert_all_kernel<<<1184, 256>>>(X, D, g_w);

    // launch 1: embed GEMM (writes unnormalized bf16 embeds + ss partials)
    dim3 ge(TOTROWS / 128, EDIM / 128);        // (189, 4)
    gemm_kernel<0><<<ge, 256, SMEM_GEMM>>>(g_b);

    // launch 2: invnorm -> ci3 (queries) + crh (exemplars)
    invnorm_kernel<<<(REALROWS + 255) / 256, 256>>>(r, h_w, h_b);

    // launch 3: main GEMM (fused cube*crh + n-reduction)  <- ncu capture slot
    dim3 gm(BQ / 128, NPAD / 128);             // (32, 157)
    gemm_kernel<1><<<gm, 256, SMEM_GEMM>>>(nullptr);

    // launch 4: final reduce + sigmoid
    reduce_kernel<<<(BQ + 127) / 128, 128>>>(out, out_size);
}